// round 6
// baseline (speedup 1.0000x reference)
#include <cuda_runtime.h>
#include <cuda_bf16.h>
#include <cstdint>

// ---------------------------------------------------------------------------
// Problem constants
// ---------------------------------------------------------------------------
#define BWIN   1024
#define BIMG   64
#define NTOK   49
#define CH     512
#define NH     16
#define HD     32
#define MTOT   (BWIN * NTOK)     // 50176
#define KDIM   512
#define BKE    32                // K elems per stage
#define KITERS (KDIM / BKE)      // 16
#define AST    40                // smem row stride (bf16 elems) = 80 bytes
#define MAT_BYTES   (128 * AST * 2)      // 10240 per matrix (Ah/Al/Bh/Bl)
#define STAGE_BYTES (4 * MAT_BYTES)      // 40960
#define SMEM_BYTES  (2 * STAGE_BYTES)    // 81920

// ---------------------------------------------------------------------------
// Scratch (__device__ globals; allocation-free rule)
// ---------------------------------------------------------------------------
__device__ float         g_kv [(size_t)MTOT * 1024];
__device__ __nv_bfloat16 g_Ah [(size_t)MTOT * KDIM];
__device__ __nv_bfloat16 g_Al [(size_t)MTOT * KDIM];
__device__ __nv_bfloat16 g_xh [(size_t)MTOT * KDIM];
__device__ __nv_bfloat16 g_xl [(size_t)MTOT * KDIM];
__device__ __nv_bfloat16 g_W1h[1024 * 512], g_W1l[1024 * 512];
__device__ __nv_bfloat16 g_W2h[ 512 * 512], g_W2l[ 512 * 512];

// ---------------------------------------------------------------------------
// Helpers
// ---------------------------------------------------------------------------
__device__ __forceinline__ uint32_t s2u(const void* p) {
    uint32_t a;
    asm("{ .reg .u64 t; cvta.to.shared.u64 t, %1; cvt.u32.u64 %0, t; }" : "=r"(a) : "l"(p));
    return a;
}

#define LDSM4(R, addr)                                                         \
    asm volatile("ldmatrix.sync.aligned.m8n8.x4.shared.b16 {%0,%1,%2,%3}, [%4];" \
                 : "=r"((R)[0]), "=r"((R)[1]), "=r"((R)[2]), "=r"((R)[3])       \
                 : "r"(addr))

#define MMA16816(Cf, Af, b0, b1)                                               \
    asm volatile("mma.sync.aligned.m16n8k16.row.col.f32.bf16.bf16.f32 "        \
                 "{%0,%1,%2,%3}, {%4,%5,%6,%7}, {%8,%9}, {%0,%1,%2,%3};"       \
                 : "+f"((Cf)[0]), "+f"((Cf)[1]), "+f"((Cf)[2]), "+f"((Cf)[3])  \
                 : "r"((Af)[0]), "r"((Af)[1]), "r"((Af)[2]), "r"((Af)[3]),     \
                   "r"(b0), "r"(b1))

// ---------------------------------------------------------------------------
// Conversion kernels
// ---------------------------------------------------------------------------
__global__ void split_kernel(const float4* __restrict__ X,
                             uint2* __restrict__ H, uint2* __restrict__ L, int n4) {
    int i = blockIdx.x * blockDim.x + threadIdx.x;
    if (i >= n4) return;
    float4 v = X[i];
    __nv_bfloat16 h0 = __float2bfloat16(v.x), h1 = __float2bfloat16(v.y);
    __nv_bfloat16 h2 = __float2bfloat16(v.z), h3 = __float2bfloat16(v.w);
    __nv_bfloat16 l0 = __float2bfloat16(v.x - __bfloat162float(h0));
    __nv_bfloat16 l1 = __float2bfloat16(v.y - __bfloat162float(h1));
    __nv_bfloat16 l2 = __float2bfloat16(v.z - __bfloat162float(h2));
    __nv_bfloat16 l3 = __float2bfloat16(v.w - __bfloat162float(h3));
    __nv_bfloat162 p01, p23, q01, q23;
    p01.x = h0; p01.y = h1; p23.x = h2; p23.y = h3;
    q01.x = l0; q01.y = l1; q23.x = l2; q23.y = l3;
    uint2 hv, lv;
    hv.x = *reinterpret_cast<unsigned*>(&p01); hv.y = *reinterpret_cast<unsigned*>(&p23);
    lv.x = *reinterpret_cast<unsigned*>(&q01); lv.y = *reinterpret_cast<unsigned*>(&q23);
    H[i] = hv; L[i] = lv;
}

__global__ void transpose_split(const float* __restrict__ W,
                                __nv_bfloat16* __restrict__ Th,
                                __nv_bfloat16* __restrict__ Tl, int K, int N) {
    __shared__ float t[32][33];
    int n0 = blockIdx.x * 32, k0 = blockIdx.y * 32;
    for (int i = threadIdx.y; i < 32; i += 8)
        t[i][threadIdx.x] = W[(size_t)(k0 + i) * N + n0 + threadIdx.x];
    __syncthreads();
    for (int i = threadIdx.y; i < 32; i += 8) {
        float v = t[threadIdx.x][i];
        __nv_bfloat16 h = __float2bfloat16(v);
        __nv_bfloat16 l = __float2bfloat16(v - __bfloat162float(h));
        Th[(size_t)(n0 + i) * K + k0 + threadIdx.x] = h;
        Tl[(size_t)(n0 + i) * K + k0 + threadIdx.x] = l;
    }
}

// ---------------------------------------------------------------------------
// mma.sync bf16 GEMM; 128x128 CTA tile, 4 warps of 64x64, 1 sync/iter
// ---------------------------------------------------------------------------
__device__ __forceinline__ void fill_stage(uint32_t sbase,
                                           const __nv_bfloat16* const srcs[4],
                                           int k0, int tid) {
    #pragma unroll
    for (int t = 0; t < 16; t++) {
        int c   = tid + t * 128;          // 0..2047
        int mat = c >> 9;
        int r   = (c >> 2) & 127;
        int ch  = c & 3;
        uint32_t dst = sbase + mat * MAT_BYTES + r * (AST * 2) + ch * 16;
        const char* src = (const char*)(srcs[mat] + (size_t)r * KDIM + k0) + ch * 16;
        asm volatile("cp.async.cg.shared.global [%0], [%1], 16;" :: "r"(dst), "l"(src));
    }
    asm volatile("cp.async.commit_group;" ::: "memory");
}

__global__ void __launch_bounds__(128) gemm_tc(
    const __nv_bfloat16* __restrict__ Ah, const __nv_bfloat16* __restrict__ Al,
    const __nv_bfloat16* __restrict__ Bh, const __nv_bfloat16* __restrict__ Bl,
    const float* __restrict__ bias, float* __restrict__ C, int N)
{
    extern __shared__ char smem[];
    const uint32_t sb = s2u(smem);
    const int tid = threadIdx.x, wid = tid >> 5, lane = tid & 31;
    const int wm = (wid & 1) * 64;
    const int wn = (wid >> 1) * 64;
    const int bM = blockIdx.y * 128, bN = blockIdx.x * 128;

    const __nv_bfloat16* srcs[4] = {
        Ah + (size_t)bM * KDIM, Al + (size_t)bM * KDIM,
        Bh + (size_t)bN * KDIM, Bl + (size_t)bN * KDIM };

    float acc[4][8][4];
    #pragma unroll
    for (int i = 0; i < 4; i++)
        #pragma unroll
        for (int j = 0; j < 8; j++)
            #pragma unroll
            for (int e = 0; e < 4; e++) acc[i][j][e] = 0.f;

    const int lrow  = lane & 15;
    const int lcolB = ((lane >> 4) << 3) * 2;

    fill_stage(sb, srcs, 0, tid);

    for (int it = 0; it < KITERS; it++) {
        asm volatile("cp.async.wait_group 0;" ::: "memory");
        __syncthreads();

        uint32_t st = sb + (it & 1) * STAGE_BYTES;
        #pragma unroll
        for (int ks = 0; ks < 2; ks++) {
            uint32_t kb = ks * 32 + lcolB;
            uint32_t ah[4][4], al[4][4], bh[4][4], bl[4][4];
            #pragma unroll
            for (int i = 0; i < 4; i++) {
                uint32_t ra = st + (wm + i * 16 + lrow) * (AST * 2) + kb;
                LDSM4(ah[i], ra);
                LDSM4(al[i], ra + MAT_BYTES);
            }
            #pragma unroll
            for (int jj = 0; jj < 4; jj++) {
                uint32_t rb = st + 2 * MAT_BYTES + (wn + jj * 16 + lrow) * (AST * 2) + kb;
                LDSM4(bh[jj], rb);
                LDSM4(bl[jj], rb + MAT_BYTES);
            }
            // prefetch next stage while MMAs run (other buffer; safe pre-barrier)
            if (ks == 0 && it + 1 < KITERS)
                fill_stage(sb + ((it + 1) & 1) * STAGE_BYTES, srcs, (it + 1) * BKE, tid);

            #pragma unroll
            for (int i = 0; i < 4; i++)
                #pragma unroll
                for (int j = 0; j < 8; j++) {
                    int jj = j >> 1, sel = j & 1;
                    MMA16816(acc[i][j], ah[i], bh[jj][sel], bh[jj][sel + 2]);
                }
            #pragma unroll
            for (int i = 0; i < 4; i++)
                #pragma unroll
                for (int j = 0; j < 8; j++) {
                    int jj = j >> 1, sel = j & 1;
                    MMA16816(acc[i][j], al[i], bh[jj][sel], bh[jj][sel + 2]);
                }
            #pragma unroll
            for (int i = 0; i < 4; i++)
                #pragma unroll
                for (int j = 0; j < 8; j++) {
                    int jj = j >> 1, sel = j & 1;
                    MMA16816(acc[i][j], ah[i], bl[jj][sel], bl[jj][sel + 2]);
                }
        }
    }

    #pragma unroll
    for (int j = 0; j < 8; j++) {
        int c0 = bN + wn + j * 8 + (lane & 3) * 2;
        float b0 = bias[c0], b1 = bias[c0 + 1];
        #pragma unroll
        for (int i = 0; i < 4; i++) {
            int r0 = bM + wm + i * 16 + (lane >> 2);
            float2 v0 = { acc[i][j][0] + b0, acc[i][j][1] + b1 };
            float2 v1 = { acc[i][j][2] + b0, acc[i][j][3] + b1 };
            *(float2*)&C[(size_t)r0 * N + c0]       = v0;
            *(float2*)&C[(size_t)(r0 + 8) * N + c0] = v1;
        }
    }
}

// ---------------------------------------------------------------------------
// Attention v3: ILP accumulators, 98-thread softmax, dual-acc AV
// ---------------------------------------------------------------------------
__global__ void __launch_bounds__(128) attn_kernel(
    const float* __restrict__ q_global,
    const float* __restrict__ bias_table)
{
    const int bh = blockIdx.x;
    const int b_ = bh >> 4;
    const int h  = bh & 15;
    const int b  = b_ >> 4;
    const int tid = threadIdx.x;

    __shared__ __align__(16) float qs[NTOK][HD];
    __shared__ __align__(16) float ks[NTOK][HD];
    __shared__ __align__(16) float vs[NTOK][HD];
    __shared__ __align__(16) float sc[NTOK][52];
    __shared__ float bias_s[169];

    const float scale = 0.17677669529663687f;

    {
        const float4* qg = (const float4*)(q_global + ((size_t)b  * NTOK) * CH + h * HD);
        const float4* kg = (const float4*)(g_kv     + ((size_t)b_ * NTOK) * 1024 + h * HD);
        for (int t = tid; t < NTOK * 8; t += 128) {
            int n = t >> 3, c = t & 7;
            float4 qv = qg[(size_t)n * (CH / 4) + c];
            qv.x *= scale; qv.y *= scale; qv.z *= scale; qv.w *= scale;
            ((float4*)qs[n])[c] = qv;
            ((float4*)ks[n])[c] = kg[(size_t)n * 256 + c];
            ((float4*)vs[n])[c] = kg[(size_t)n * 256 + 128 + c];
        }
        for (int t = tid; t < 169; t += 128) bias_s[t] = bias_table[t * NH + h];
    }
    __syncthreads();

    // ---- scores: thread = (row i, half of j); 4 independent accumulators ----
    {
        int i = tid >> 1, half = tid & 1;
        if (i < NTOK) {
            float4 q0 = ((const float4*)qs[i])[0], q1 = ((const float4*)qs[i])[1];
            float4 q2 = ((const float4*)qs[i])[2], q3 = ((const float4*)qs[i])[3];
            float4 q4 = ((const float4*)qs[i])[4], q5 = ((const float4*)qs[i])[5];
            float4 q6 = ((const float4*)qs[i])[6], q7 = ((const float4*)qs[i])[7];
            int ih = i / 7, iw = i - ih * 7;
            int j0 = half ? 25 : 0, j1 = half ? NTOK : 25;
            for (int j = j0; j < j1; j++) {
                const float4* kr = (const float4*)ks[j];
                float4 k0 = kr[0], k1 = kr[1], k2 = kr[2], k3 = kr[3];
                float4 k4 = kr[4], k5 = kr[5], k6 = kr[6], k7 = kr[7];
                float s0 = q0.x*k0.x + q0.y*k0.y + q0.z*k0.z + q0.w*k0.w
                         + q1.x*k1.x + q1.y*k1.y + q1.z*k1.z + q1.w*k1.w;
                float s1 = q2.x*k2.x + q2.y*k2.y + q2.z*k2.z + q2.w*k2.w
                         + q3.x*k3.x + q3.y*k3.y + q3.z*k3.z + q3.w*k3.w;
                float s2 = q4.x*k4.x + q4.y*k4.y + q4.z*k4.z + q4.w*k4.w
                         + q5.x*k5.x + q5.y*k5.y + q5.z*k5.z + q5.w*k5.w;
                float s3 = q6.x*k6.x + q6.y*k6.y + q6.z*k6.z + q6.w*k6.w
                         + q7.x*k7.x + q7.y*k7.y + q7.z*k7.z + q7.w*k7.w;
                int jh = j / 7, jw = j - jh * 7;
                int idx = (ih - jh + 6) * 13 + (iw - jw + 6);
                sc[i][j] = (s0 + s1) + (s2 + s3) + bias_s[idx];
            }
        }
    }
    __syncthreads();

    // ---- softmax: 98 threads, pair (half) combine via shfl ----
    if (tid < 2 * NTOK) {
        int i = tid >> 1, half = tid & 1;
        unsigned mask = __activemask();
        float4* srow = (float4*)sc[i];
        int c0 = half * 6;
        float m = -1e30f;
        #pragma unroll
        for (int c = 0; c < 6; c++) {
            float4 v = srow[c0 + c];
            m = fmaxf(m, fmaxf(fmaxf(v.x, v.y), fmaxf(v.z, v.w)));
        }
        if (half) m = fmaxf(m, sc[i][48]);
        m = fmaxf(m, __shfl_xor_sync(mask, m, 1));
        float s = 0.f;
        #pragma unroll
        for (int c = 0; c < 6; c++) {
            float4 v = srow[c0 + c];
            v.x = __expf(v.x - m); v.y = __expf(v.y - m);
            v.z = __expf(v.z - m); v.w = __expf(v.w - m);
            s += (v.x + v.y) + (v.z + v.w);
            srow[c0 + c] = v;
        }
        float e48 = 0.f;
        if (half) { e48 = __expf(sc[i][48] - m); s += e48; }
        s += __shfl_xor_sync(mask, s, 1);
        float inv = 1.0f / s;
        #pragma unroll
        for (int c = 0; c < 6; c++) {
            float4 v = srow[c0 + c];
            v.x *= inv; v.y *= inv; v.z *= inv; v.w *= inv;
            srow[c0 + c] = v;
        }
        if (half) sc[i][48] = e48 * inv;
    }
    __syncthreads();

    // ---- x = attn @ v : dual accumulators ----
    for (int t = tid; t < NTOK * 8; t += 128) {
        int i = t >> 3, d4 = t & 7;
        float4 a = {0.f, 0.f, 0.f, 0.f};
        float4 b4 = {0.f, 0.f, 0.f, 0.f};
        #pragma unroll
        for (int j = 0; j < 48; j += 2) {
            float w0 = sc[i][j], w1 = sc[i][j + 1];
            float4 v0 = ((const float4*)vs[j])[d4];
            float4 v1 = ((const float4*)vs[j + 1])[d4];
            a.x += w0 * v0.x; a.y += w0 * v0.y; a.z += w0 * v0.z; a.w += w0 * v0.w;
            b4.x += w1 * v1.x; b4.y += w1 * v1.y; b4.z += w1 * v1.z; b4.w += w1 * v1.w;
        }
        {
            float w = sc[i][48];
            float4 vv = ((const float4*)vs[48])[d4];
            a.x += w * vv.x; a.y += w * vv.y; a.z += w * vv.z; a.w += w * vv.w;
        }
        a.x += b4.x; a.y += b4.y; a.z += b4.z; a.w += b4.w;
        size_t off = ((size_t)(b_ * NTOK + i)) * CH + h * HD + d4 * 4;
        __nv_bfloat16 h0 = __float2bfloat16(a.x), h1 = __float2bfloat16(a.y);
        __nv_bfloat16 h2 = __float2bfloat16(a.z), h3 = __float2bfloat16(a.w);
        __nv_bfloat16 l0 = __float2bfloat16(a.x - __bfloat162float(h0));
        __nv_bfloat16 l1 = __float2bfloat16(a.y - __bfloat162float(h1));
        __nv_bfloat16 l2 = __float2bfloat16(a.z - __bfloat162float(h2));
        __nv_bfloat16 l3 = __float2bfloat16(a.w - __bfloat162float(h3));
        __nv_bfloat162 ph0, ph1, pl0, pl1;
        ph0.x = h0; ph0.y = h1; ph1.x = h2; ph1.y = h3;
        pl0.x = l0; pl0.y = l1; pl1.x = l2; pl1.y = l3;
        uint2 hv, lv;
        hv.x = *reinterpret_cast<unsigned*>(&ph0); hv.y = *reinterpret_cast<unsigned*>(&ph1);
        lv.x = *reinterpret_cast<unsigned*>(&pl0); lv.y = *reinterpret_cast<unsigned*>(&pl1);
        *(uint2*)(g_xh + off) = hv;
        *(uint2*)(g_xl + off) = lv;
    }
}

// ---------------------------------------------------------------------------
// Launch
// ---------------------------------------------------------------------------
extern "C" void kernel_launch(void* const* d_in, const int* in_sizes, int n_in,
                              void* d_out, int out_size)
{
    const float* inputs     = (const float*)d_in[0];
    const float* q_global   = (const float*)d_in[1];
    const float* qkv_w      = (const float*)d_in[2];
    const float* qkv_b      = (const float*)d_in[3];
    const float* bias_table = (const float*)d_in[4];
    const float* proj_w     = (const float*)d_in[5];
    const float* proj_b     = (const float*)d_in[6];
    float*       out        = (float*)d_out;

    float *kv_ptr;
    __nv_bfloat16 *Ah, *Al, *Xh, *Xl, *W1h, *W1l, *W2h, *W2l;
    cudaGetSymbolAddress((void**)&kv_ptr, g_kv);
    cudaGetSymbolAddress((void**)&Ah,  g_Ah);
    cudaGetSymbolAddress((void**)&Al,  g_Al);
    cudaGetSymbolAddress((void**)&Xh,  g_xh);
    cudaGetSymbolAddress((void**)&Xl,  g_xl);
    cudaGetSymbolAddress((void**)&W1h, g_W1h);
    cudaGetSymbolAddress((void**)&W1l, g_W1l);
    cudaGetSymbolAddress((void**)&W2h, g_W2h);
    cudaGetSymbolAddress((void**)&W2l, g_W2l);

    cudaFuncSetAttribute(gemm_tc, cudaFuncAttributeMaxDynamicSharedMemorySize, SMEM_BYTES);

    {
        int n4 = MTOT * KDIM / 4;
        split_kernel<<<(n4 + 255) / 256, 256>>>((const float4*)inputs, (uint2*)Ah, (uint2*)Al, n4);
        transpose_split<<<dim3(1024 / 32, 512 / 32), dim3(32, 8)>>>(qkv_w, W1h, W1l, 512, 1024);
        transpose_split<<<dim3(512 / 32, 512 / 32), dim3(32, 8)>>>(proj_w, W2h, W2l, 512, 512);
    }

    gemm_tc<<<dim3(1024 / 128, MTOT / 128), 128, SMEM_BYTES>>>(Ah, Al, W1h, W1l, qkv_b, kv_ptr, 1024);

    attn_kernel<<<BWIN * NH, 128>>>(q_global, bias_table);

    gemm_tc<<<dim3(512 / 128, MTOT / 128), 128, SMEM_BYTES>>>(Xh, Xl, W2h, W2l, proj_b, out, 512);
}

// round 7
// speedup vs baseline: 1.2454x; 1.2454x over previous
#include <cuda_runtime.h>
#include <cuda_fp16.h>
#include <cstdint>

// ---------------------------------------------------------------------------
// Problem constants
// ---------------------------------------------------------------------------
#define BWIN   1024
#define BIMG   64
#define NTOK   49
#define CH     512
#define NH     16
#define HD     32
#define MTOT   (BWIN * NTOK)     // 50176
#define KDIM   512
#define BKE    32                // K elems per stage
#define KITERS (KDIM / BKE)      // 16
#define AST    40                // smem row stride (fp16 elems) = 80 bytes
#define MAT_BYTES   (128 * AST * 2)      // 10240 per matrix (Ah/Al/Bh)
#define STAGE_BYTES (3 * MAT_BYTES)      // 30720
#define SMEM_BYTES  (2 * STAGE_BYTES)    // 61440

// ---------------------------------------------------------------------------
// Scratch (__device__ globals; allocation-free rule)
// ---------------------------------------------------------------------------
__device__ float  g_kv [(size_t)MTOT * 1024];
__device__ __half g_Ah [(size_t)MTOT * KDIM];
__device__ __half g_Al [(size_t)MTOT * KDIM];
__device__ __half g_xh [(size_t)MTOT * KDIM];
__device__ __half g_xl [(size_t)MTOT * KDIM];
__device__ __half g_W1h[1024 * 512];
__device__ __half g_W2h[ 512 * 512];

// ---------------------------------------------------------------------------
// Helpers
// ---------------------------------------------------------------------------
__device__ __forceinline__ uint32_t s2u(const void* p) {
    uint32_t a;
    asm("{ .reg .u64 t; cvta.to.shared.u64 t, %1; cvt.u32.u64 %0, t; }" : "=r"(a) : "l"(p));
    return a;
}

#define LDSM4(R, addr)                                                         \
    asm volatile("ldmatrix.sync.aligned.m8n8.x4.shared.b16 {%0,%1,%2,%3}, [%4];" \
                 : "=r"((R)[0]), "=r"((R)[1]), "=r"((R)[2]), "=r"((R)[3])       \
                 : "r"(addr))

#define MMA16816(Cf, Af, b0, b1)                                               \
    asm volatile("mma.sync.aligned.m16n8k16.row.col.f32.f16.f16.f32 "          \
                 "{%0,%1,%2,%3}, {%4,%5,%6,%7}, {%8,%9}, {%0,%1,%2,%3};"       \
                 : "+f"((Cf)[0]), "+f"((Cf)[1]), "+f"((Cf)[2]), "+f"((Cf)[3])  \
                 : "r"((Af)[0]), "r"((Af)[1]), "r"((Af)[2]), "r"((Af)[3]),     \
                   "r"(b0), "r"(b1))

// ---------------------------------------------------------------------------
// Conversion kernels
// ---------------------------------------------------------------------------
__global__ void split_kernel(const float4* __restrict__ X,
                             uint2* __restrict__ H, uint2* __restrict__ L, int n4) {
    int i = blockIdx.x * blockDim.x + threadIdx.x;
    if (i >= n4) return;
    float4 v = X[i];
    __half h0 = __float2half_rn(v.x), h1 = __float2half_rn(v.y);
    __half h2 = __float2half_rn(v.z), h3 = __float2half_rn(v.w);
    __half l0 = __float2half_rn(v.x - __half2float(h0));
    __half l1 = __float2half_rn(v.y - __half2float(h1));
    __half l2 = __float2half_rn(v.z - __half2float(h2));
    __half l3 = __float2half_rn(v.w - __half2float(h3));
    __half2 p01, p23, q01, q23;
    p01.x = h0; p01.y = h1; p23.x = h2; p23.y = h3;
    q01.x = l0; q01.y = l1; q23.x = l2; q23.y = l3;
    uint2 hv, lv;
    hv.x = *reinterpret_cast<unsigned*>(&p01); hv.y = *reinterpret_cast<unsigned*>(&p23);
    lv.x = *reinterpret_cast<unsigned*>(&q01); lv.y = *reinterpret_cast<unsigned*>(&q23);
    H[i] = hv; L[i] = lv;
}

// W [K,N] fp32 -> Th [N,K] fp16 (single rounding; residual dropped by design)
__global__ void transpose_h(const float* __restrict__ W,
                            __half* __restrict__ Th, int K, int N) {
    __shared__ float t[32][33];
    int n0 = blockIdx.x * 32, k0 = blockIdx.y * 32;
    for (int i = threadIdx.y; i < 32; i += 8)
        t[i][threadIdx.x] = W[(size_t)(k0 + i) * N + n0 + threadIdx.x];
    __syncthreads();
    for (int i = threadIdx.y; i < 32; i += 8)
        Th[(size_t)(n0 + i) * K + k0 + threadIdx.x] = __float2half_rn(t[threadIdx.x][i]);
}

// ---------------------------------------------------------------------------
// mma.sync fp16 2-pass GEMM: C = (Ah+Al)[M,K] @ Bh[N,K]^T + bias
// 128x128 CTA tile, 8 warps of 64x32, double-buffered cp.async
// ---------------------------------------------------------------------------
__device__ __forceinline__ void fill_stage(uint32_t sbase,
                                           const __half* const srcs[3],
                                           int k0, int tid) {
    #pragma unroll
    for (int t = 0; t < 6; t++) {
        int c   = tid + t * 256;          // 0..1535
        int mat = c >> 9;                 // 0..2
        int r   = (c >> 2) & 127;
        int ch  = c & 3;
        uint32_t dst = sbase + mat * MAT_BYTES + r * (AST * 2) + ch * 16;
        const char* src = (const char*)(srcs[mat] + (size_t)r * KDIM + k0) + ch * 16;
        asm volatile("cp.async.cg.shared.global [%0], [%1], 16;" :: "r"(dst), "l"(src));
    }
    asm volatile("cp.async.commit_group;" ::: "memory");
}

__global__ void __launch_bounds__(256, 2) gemm_tc(
    const __half* __restrict__ Ah, const __half* __restrict__ Al,
    const __half* __restrict__ Bh,
    const float* __restrict__ bias, float* __restrict__ C, int N)
{
    extern __shared__ char smem[];
    const uint32_t sb = s2u(smem);
    const int tid = threadIdx.x, wid = tid >> 5, lane = tid & 31;
    const int wm = (wid & 1) * 64;
    const int wn = (wid >> 1) * 32;
    const int bM = blockIdx.y * 128, bN = blockIdx.x * 128;

    const __half* srcs[3] = {
        Ah + (size_t)bM * KDIM, Al + (size_t)bM * KDIM, Bh + (size_t)bN * KDIM };

    float acc[4][4][4];
    #pragma unroll
    for (int i = 0; i < 4; i++)
        #pragma unroll
        for (int j = 0; j < 4; j++)
            #pragma unroll
            for (int e = 0; e < 4; e++) acc[i][j][e] = 0.f;

    const int lrow  = lane & 15;
    const int lcolB = ((lane >> 4) << 3) * 2;

    fill_stage(sb, srcs, 0, tid);

    for (int it = 0; it < KITERS; it++) {
        asm volatile("cp.async.wait_group 0;" ::: "memory");
        __syncthreads();

        uint32_t st = sb + (it & 1) * STAGE_BYTES;
        #pragma unroll
        for (int ks = 0; ks < 2; ks++) {
            uint32_t kb = ks * 32 + lcolB;
            uint32_t ah[4][4], al[4][4], bh[2][4];
            #pragma unroll
            for (int i = 0; i < 4; i++) {
                uint32_t ra = st + (wm + i * 16 + lrow) * (AST * 2) + kb;
                LDSM4(ah[i], ra);
                LDSM4(al[i], ra + MAT_BYTES);
            }
            #pragma unroll
            for (int jj = 0; jj < 2; jj++) {
                uint32_t rb = st + 2 * MAT_BYTES + (wn + jj * 16 + lrow) * (AST * 2) + kb;
                LDSM4(bh[jj], rb);
            }
            // prefetch next stage into the other buffer while MMAs run
            if (ks == 0 && it + 1 < KITERS)
                fill_stage(sb + ((it + 1) & 1) * STAGE_BYTES, srcs, (it + 1) * BKE, tid);

            #pragma unroll
            for (int i = 0; i < 4; i++)
                #pragma unroll
                for (int j = 0; j < 4; j++) {
                    int jj = j >> 1, sel = j & 1;
                    MMA16816(acc[i][j], ah[i], bh[jj][sel], bh[jj][sel + 2]);
                }
            #pragma unroll
            for (int i = 0; i < 4; i++)
                #pragma unroll
                for (int j = 0; j < 4; j++) {
                    int jj = j >> 1, sel = j & 1;
                    MMA16816(acc[i][j], al[i], bh[jj][sel], bh[jj][sel + 2]);
                }
        }
    }

    #pragma unroll
    for (int j = 0; j < 4; j++) {
        int c0 = bN + wn + j * 8 + (lane & 3) * 2;
        float b0 = bias[c0], b1 = bias[c0 + 1];
        #pragma unroll
        for (int i = 0; i < 4; i++) {
            int r0 = bM + wm + i * 16 + (lane >> 2);
            float2 v0 = { acc[i][j][0] + b0, acc[i][j][1] + b1 };
            float2 v1 = { acc[i][j][2] + b0, acc[i][j][3] + b1 };
            *(float2*)&C[(size_t)r0 * N + c0]       = v0;
            *(float2*)&C[(size_t)(r0 + 8) * N + c0] = v1;
        }
    }
}

// ---------------------------------------------------------------------------
// Attention (round-5 proven version), fp16 hi/lo outputs
// ---------------------------------------------------------------------------
__global__ void __launch_bounds__(128) attn_kernel(
    const float* __restrict__ q_global,
    const float* __restrict__ bias_table)
{
    const int bh = blockIdx.x;
    const int b_ = bh >> 4;
    const int h  = bh & 15;
    const int b  = b_ >> 4;
    const int tid = threadIdx.x;

    __shared__ __align__(16) float qs[NTOK][HD];
    __shared__ __align__(16) float ks[NTOK][HD];
    __shared__ __align__(16) float vs[NTOK][HD];
    __shared__ __align__(16) float sc[NTOK][52];
    __shared__ float bias_s[169];

    const float scale = 0.17677669529663687f;

    {
        const float4* qg = (const float4*)(q_global + ((size_t)b  * NTOK) * CH + h * HD);
        const float4* kg = (const float4*)(g_kv     + ((size_t)b_ * NTOK) * 1024 + h * HD);
        for (int t = tid; t < NTOK * 8; t += 128) {
            int n = t >> 3, c = t & 7;
            float4 qv = qg[(size_t)n * (CH / 4) + c];
            qv.x *= scale; qv.y *= scale; qv.z *= scale; qv.w *= scale;
            ((float4*)qs[n])[c] = qv;
            ((float4*)ks[n])[c] = kg[(size_t)n * 256 + c];
            ((float4*)vs[n])[c] = kg[(size_t)n * 256 + 128 + c];
        }
        for (int t = tid; t < 169; t += 128) bias_s[t] = bias_table[t * NH + h];
    }
    __syncthreads();

    {
        int i = tid >> 1, half = tid & 1;
        if (i < NTOK) {
            float4 q0 = ((const float4*)qs[i])[0], q1 = ((const float4*)qs[i])[1];
            float4 q2 = ((const float4*)qs[i])[2], q3 = ((const float4*)qs[i])[3];
            float4 q4 = ((const float4*)qs[i])[4], q5 = ((const float4*)qs[i])[5];
            float4 q6 = ((const float4*)qs[i])[6], q7 = ((const float4*)qs[i])[7];
            int ih = i / 7, iw = i - ih * 7;
            int j0 = half ? 25 : 0, j1 = half ? NTOK : 25;
            for (int j = j0; j < j1; j++) {
                const float4* kr = (const float4*)ks[j];
                float4 k0 = kr[0], k1 = kr[1], k2 = kr[2], k3 = kr[3];
                float4 k4 = kr[4], k5 = kr[5], k6 = kr[6], k7 = kr[7];
                float s0 = q0.x*k0.x + q0.y*k0.y + q0.z*k0.z + q0.w*k0.w
                         + q1.x*k1.x + q1.y*k1.y + q1.z*k1.z + q1.w*k1.w;
                float s1 = q2.x*k2.x + q2.y*k2.y + q2.z*k2.z + q2.w*k2.w
                         + q3.x*k3.x + q3.y*k3.y + q3.z*k3.z + q3.w*k3.w;
                float s2 = q4.x*k4.x + q4.y*k4.y + q4.z*k4.z + q4.w*k4.w
                         + q5.x*k5.x + q5.y*k5.y + q5.z*k5.z + q5.w*k5.w;
                float s3 = q6.x*k6.x + q6.y*k6.y + q6.z*k6.z + q6.w*k6.w
                         + q7.x*k7.x + q7.y*k7.y + q7.z*k7.z + q7.w*k7.w;
                int jh = j / 7, jw = j - jh * 7;
                int idx = (ih - jh + 6) * 13 + (iw - jw + 6);
                sc[i][j] = (s0 + s1) + (s2 + s3) + bias_s[idx];
            }
        }
    }
    __syncthreads();

    if (tid < NTOK) {
        float4* srow = (float4*)sc[tid];
        float m = sc[tid][48];
        #pragma unroll
        for (int c = 0; c < 12; c++) {
            float4 v = srow[c];
            m = fmaxf(m, fmaxf(fmaxf(v.x, v.y), fmaxf(v.z, v.w)));
        }
        float s = 0.f;
        #pragma unroll
        for (int c = 0; c < 12; c++) {
            float4 v = srow[c];
            v.x = __expf(v.x - m); v.y = __expf(v.y - m);
            v.z = __expf(v.z - m); v.w = __expf(v.w - m);
            s += (v.x + v.y) + (v.z + v.w);
            srow[c] = v;
        }
        float e48 = __expf(sc[tid][48] - m);
        s += e48;
        float inv = 1.0f / s;
        #pragma unroll
        for (int c = 0; c < 12; c++) {
            float4 v = srow[c];
            v.x *= inv; v.y *= inv; v.z *= inv; v.w *= inv;
            srow[c] = v;
        }
        sc[tid][48] = e48 * inv;
    }
    __syncthreads();

    for (int t = tid; t < NTOK * 8; t += 128) {
        int i = t >> 3, d4 = t & 7;
        float4 a = {0.f, 0.f, 0.f, 0.f};
        float4 b4 = {0.f, 0.f, 0.f, 0.f};
        #pragma unroll
        for (int j = 0; j < 48; j += 2) {
            float w0 = sc[i][j], w1 = sc[i][j + 1];
            float4 v0 = ((const float4*)vs[j])[d4];
            float4 v1 = ((const float4*)vs[j + 1])[d4];
            a.x += w0 * v0.x; a.y += w0 * v0.y; a.z += w0 * v0.z; a.w += w0 * v0.w;
            b4.x += w1 * v1.x; b4.y += w1 * v1.y; b4.z += w1 * v1.z; b4.w += w1 * v1.w;
        }
        {
            float w = sc[i][48];
            float4 vv = ((const float4*)vs[48])[d4];
            a.x += w * vv.x; a.y += w * vv.y; a.z += w * vv.z; a.w += w * vv.w;
        }
        a.x += b4.x; a.y += b4.y; a.z += b4.z; a.w += b4.w;
        size_t off = ((size_t)(b_ * NTOK + i)) * CH + h * HD + d4 * 4;
        __half h0 = __float2half_rn(a.x), h1 = __float2half_rn(a.y);
        __half h2 = __float2half_rn(a.z), h3 = __float2half_rn(a.w);
        __half l0 = __float2half_rn(a.x - __half2float(h0));
        __half l1 = __float2half_rn(a.y - __half2float(h1));
        __half l2 = __float2half_rn(a.z - __half2float(h2));
        __half l3 = __float2half_rn(a.w - __half2float(h3));
        __half2 ph0, ph1, pl0, pl1;
        ph0.x = h0; ph0.y = h1; ph1.x = h2; ph1.y = h3;
        pl0.x = l0; pl0.y = l1; pl1.x = l2; pl1.y = l3;
        uint2 hv, lv;
        hv.x = *reinterpret_cast<unsigned*>(&ph0); hv.y = *reinterpret_cast<unsigned*>(&ph1);
        lv.x = *reinterpret_cast<unsigned*>(&pl0); lv.y = *reinterpret_cast<unsigned*>(&pl1);
        *(uint2*)(g_xh + off) = hv;
        *(uint2*)(g_xl + off) = lv;
    }
}

// ---------------------------------------------------------------------------
// Launch
// ---------------------------------------------------------------------------
extern "C" void kernel_launch(void* const* d_in, const int* in_sizes, int n_in,
                              void* d_out, int out_size)
{
    const float* inputs     = (const float*)d_in[0];
    const float* q_global   = (const float*)d_in[1];
    const float* qkv_w      = (const float*)d_in[2];
    const float* qkv_b      = (const float*)d_in[3];
    const float* bias_table = (const float*)d_in[4];
    const float* proj_w     = (const float*)d_in[5];
    const float* proj_b     = (const float*)d_in[6];
    float*       out        = (float*)d_out;

    float *kv_ptr;
    __half *Ah, *Al, *Xh, *Xl, *W1h, *W2h;
    cudaGetSymbolAddress((void**)&kv_ptr, g_kv);
    cudaGetSymbolAddress((void**)&Ah,  g_Ah);
    cudaGetSymbolAddress((void**)&Al,  g_Al);
    cudaGetSymbolAddress((void**)&Xh,  g_xh);
    cudaGetSymbolAddress((void**)&Xl,  g_xl);
    cudaGetSymbolAddress((void**)&W1h, g_W1h);
    cudaGetSymbolAddress((void**)&W2h, g_W2h);

    cudaFuncSetAttribute(gemm_tc, cudaFuncAttributeMaxDynamicSharedMemorySize, SMEM_BYTES);

    {
        int n4 = MTOT * KDIM / 4;
        split_kernel<<<(n4 + 255) / 256, 256>>>((const float4*)inputs, (uint2*)Ah, (uint2*)Al, n4);
        transpose_h<<<dim3(1024 / 32, 512 / 32), dim3(32, 8)>>>(qkv_w, W1h, 512, 1024);
        transpose_h<<<dim3(512 / 32, 512 / 32), dim3(32, 8)>>>(proj_w, W2h, 512, 512);
    }

    gemm_tc<<<dim3(1024 / 128, MTOT / 128), 256, SMEM_BYTES>>>(Ah, Al, W1h, qkv_b, kv_ptr, 1024);

    attn_kernel<<<BWIN * NH, 128>>>(q_global, bias_table);

    gemm_tc<<<dim3(512 / 128, MTOT / 128), 256, SMEM_BYTES>>>(Xh, Xl, W2h, proj_b, out, 512);
}

// round 9
// speedup vs baseline: 1.8876x; 1.5156x over previous
#include <cuda_runtime.h>
#include <cuda_fp16.h>
#include <cstdint>

// ---------------------------------------------------------------------------
// Problem constants
// ---------------------------------------------------------------------------
#define BWIN   1024
#define NTOK   49
#define CH     512
#define NH     16
#define HD     32
#define MTOT   (BWIN * NTOK)     // 50176
#define KDIM   512
#define BKE    32
#define KITERS (KDIM / BKE)      // 16
#define AST    40                // smem row stride (fp16 elems)
#define MAT_BYTES   (128 * AST * 2)
#define STAGE_BYTES (3 * MAT_BYTES)
#define SMEM_BYTES  (2 * STAGE_BYTES)
#define SCALE  0.17677669529663687f

// ---------------------------------------------------------------------------
// Scratch
// ---------------------------------------------------------------------------
__device__ __half g_kv [(size_t)MTOT * 1024];   // kv projection, fp16
__device__ __half g_Ah [(size_t)MTOT * KDIM];
__device__ __half g_Al [(size_t)MTOT * KDIM];
__device__ __half g_xh [(size_t)MTOT * KDIM];
__device__ __half g_xl [(size_t)MTOT * KDIM];
__device__ __half g_W1h[1024 * 512];
__device__ __half g_W2h[ 512 * 512];

// ---------------------------------------------------------------------------
// Helpers
// ---------------------------------------------------------------------------
__device__ __forceinline__ uint32_t s2u(const void* p) {
    uint32_t a;
    asm("{ .reg .u64 t; cvta.to.shared.u64 t, %1; cvt.u32.u64 %0, t; }" : "=r"(a) : "l"(p));
    return a;
}

#define LDSM4(R, addr)                                                         \
    asm volatile("ldmatrix.sync.aligned.m8n8.x4.shared.b16 {%0,%1,%2,%3}, [%4];" \
                 : "=r"((R)[0]), "=r"((R)[1]), "=r"((R)[2]), "=r"((R)[3])       \
                 : "r"(addr))

#define LDSM4T(R, addr)                                                        \
    asm volatile("ldmatrix.sync.aligned.m8n8.x4.trans.shared.b16 {%0,%1,%2,%3}, [%4];" \
                 : "=r"((R)[0]), "=r"((R)[1]), "=r"((R)[2]), "=r"((R)[3])       \
                 : "r"(addr))

#define MMA16816(Cf, Af, b0, b1)                                               \
    asm volatile("mma.sync.aligned.m16n8k16.row.col.f32.f16.f16.f32 "          \
                 "{%0,%1,%2,%3}, {%4,%5,%6,%7}, {%8,%9}, {%0,%1,%2,%3};"       \
                 : "+f"((Cf)[0]), "+f"((Cf)[1]), "+f"((Cf)[2]), "+f"((Cf)[3])  \
                 : "r"((Af)[0]), "r"((Af)[1]), "r"((Af)[2]), "r"((Af)[3]),     \
                   "r"(b0), "r"(b1))

__device__ __forceinline__ uint32_t packh2(float a, float b) {
    __half2 h = __floats2half2_rn(a, b);
    return *reinterpret_cast<uint32_t*>(&h);
}

// ---------------------------------------------------------------------------
// Conversion kernels
// ---------------------------------------------------------------------------
__global__ void split_kernel(const float4* __restrict__ X,
                             uint2* __restrict__ H, uint2* __restrict__ L, int n4) {
    int i = blockIdx.x * blockDim.x + threadIdx.x;
    if (i >= n4) return;
    float4 v = X[i];
    __half h0 = __float2half_rn(v.x), h1 = __float2half_rn(v.y);
    __half h2 = __float2half_rn(v.z), h3 = __float2half_rn(v.w);
    uint2 hv, lv;
    hv.x = packh2(v.x, v.y); hv.y = packh2(v.z, v.w);
    lv.x = packh2(v.x - __half2float(h0), v.y - __half2float(h1));
    lv.y = packh2(v.z - __half2float(h2), v.w - __half2float(h3));
    H[i] = hv; L[i] = lv;
}

__global__ void transpose_h(const float* __restrict__ W,
                            __half* __restrict__ Th, int K, int N) {
    __shared__ float t[32][33];
    int n0 = blockIdx.x * 32, k0 = blockIdx.y * 32;
    for (int i = threadIdx.y; i < 32; i += 8)
        t[i][threadIdx.x] = W[(size_t)(k0 + i) * N + n0 + threadIdx.x];
    __syncthreads();
    for (int i = threadIdx.y; i < 32; i += 8)
        Th[(size_t)(n0 + i) * K + k0 + threadIdx.x] = __float2half_rn(t[threadIdx.x][i]);
}

// ---------------------------------------------------------------------------
// fp16 2-pass GEMM: C = (Ah+Al)[M,K] @ Bh[N,K]^T + bias ; C fp32 or fp16
// ---------------------------------------------------------------------------
__device__ __forceinline__ void fill_stage(uint32_t sbase,
                                           const __half* const srcs[3],
                                           int k0, int tid) {
    #pragma unroll
    for (int t = 0; t < 6; t++) {
        int c   = tid + t * 256;
        int mat = c >> 9;
        int r   = (c >> 2) & 127;
        int ch  = c & 3;
        uint32_t dst = sbase + mat * MAT_BYTES + r * (AST * 2) + ch * 16;
        const char* src = (const char*)(srcs[mat] + (size_t)r * KDIM + k0) + ch * 16;
        asm volatile("cp.async.cg.shared.global [%0], [%1], 16;" :: "r"(dst), "l"(src));
    }
    asm volatile("cp.async.commit_group;" ::: "memory");
}

template<bool OUTH>
__global__ void __launch_bounds__(256, 2) gemm_tc(
    const __half* __restrict__ Ah, const __half* __restrict__ Al,
    const __half* __restrict__ Bh,
    const float* __restrict__ bias, void* __restrict__ Cv, int N)
{
    extern __shared__ char smem[];
    const uint32_t sb = s2u(smem);
    const int tid = threadIdx.x, wid = tid >> 5, lane = tid & 31;
    const int wm = (wid & 1) * 64;
    const int wn = (wid >> 1) * 32;
    const int bM = blockIdx.y * 128, bN = blockIdx.x * 128;

    const __half* srcs[3] = {
        Ah + (size_t)bM * KDIM, Al + (size_t)bM * KDIM, Bh + (size_t)bN * KDIM };

    float acc[4][4][4];
    #pragma unroll
    for (int i = 0; i < 4; i++)
        #pragma unroll
        for (int j = 0; j < 4; j++)
            #pragma unroll
            for (int e = 0; e < 4; e++) acc[i][j][e] = 0.f;

    const int lrow  = lane & 15;
    const int lcolB = ((lane >> 4) << 3) * 2;

    fill_stage(sb, srcs, 0, tid);

    for (int it = 0; it < KITERS; it++) {
        asm volatile("cp.async.wait_group 0;" ::: "memory");
        __syncthreads();

        uint32_t st = sb + (it & 1) * STAGE_BYTES;
        #pragma unroll
        for (int ks = 0; ks < 2; ks++) {
            uint32_t kb = ks * 32 + lcolB;
            uint32_t ah[4][4], al[4][4], bh[2][4];
            #pragma unroll
            for (int i = 0; i < 4; i++) {
                uint32_t ra = st + (wm + i * 16 + lrow) * (AST * 2) + kb;
                LDSM4(ah[i], ra);
                LDSM4(al[i], ra + MAT_BYTES);
            }
            #pragma unroll
            for (int jj = 0; jj < 2; jj++) {
                uint32_t rb = st + 2 * MAT_BYTES + (wn + jj * 16 + lrow) * (AST * 2) + kb;
                LDSM4(bh[jj], rb);
            }
            if (ks == 0 && it + 1 < KITERS)
                fill_stage(sb + ((it + 1) & 1) * STAGE_BYTES, srcs, (it + 1) * BKE, tid);

            #pragma unroll
            for (int i = 0; i < 4; i++)
                #pragma unroll
                for (int j = 0; j < 4; j++) {
                    int jj = j >> 1, sel = j & 1;
                    MMA16816(acc[i][j], ah[i], bh[jj][sel], bh[jj][sel + 2]);
                }
            #pragma unroll
            for (int i = 0; i < 4; i++)
                #pragma unroll
                for (int j = 0; j < 4; j++) {
                    int jj = j >> 1, sel = j & 1;
                    MMA16816(acc[i][j], al[i], bh[jj][sel], bh[jj][sel + 2]);
                }
        }
    }

    #pragma unroll
    for (int j = 0; j < 4; j++) {
        int c0 = bN + wn + j * 8 + (lane & 3) * 2;
        float b0 = bias[c0], b1 = bias[c0 + 1];
        #pragma unroll
        for (int i = 0; i < 4; i++) {
            int r0 = bM + wm + i * 16 + (lane >> 2);
            if (OUTH) {
                __half* C = (__half*)Cv;
                __half2 v0 = __floats2half2_rn(acc[i][j][0] + b0, acc[i][j][1] + b1);
                __half2 v1 = __floats2half2_rn(acc[i][j][2] + b0, acc[i][j][3] + b1);
                *(__half2*)&C[(size_t)r0 * N + c0]       = v0;
                *(__half2*)&C[(size_t)(r0 + 8) * N + c0] = v1;
            } else {
                float* C = (float*)Cv;
                float2 v0 = { acc[i][j][0] + b0, acc[i][j][1] + b1 };
                float2 v1 = { acc[i][j][2] + b0, acc[i][j][3] + b1 };
                *(float2*)&C[(size_t)r0 * N + c0]       = v0;
                *(float2*)&C[(size_t)(r0 + 8) * N + c0] = v1;
            }
        }
    }
}

// ---------------------------------------------------------------------------
// Tensor-core attention: block = (window, head); 64x64 padded tiles
// S = Q K^T (fp16 mma) + bias, masked softmax in registers, X = P V (fp16 mma)
// ---------------------------------------------------------------------------
__global__ void __launch_bounds__(128) attn_tc(
    const float* __restrict__ q_global,
    const float* __restrict__ bias_table)
{
    const int bh = blockIdx.x;
    const int b_ = bh >> 4, h = bh & 15, b = b_ >> 4;
    const int tid = threadIdx.x, wid = tid >> 5, lane = tid & 31;

    __shared__ __align__(16) __half Qh[64 * 40];
    __shared__ __align__(16) __half Kh[64 * 40];
    __shared__ __align__(16) __half Vh[64 * 40];
    __shared__ float bias_s[172];

    // zero pad rows 49..63 (15 rows x 40 halves = 300 u32 contiguous)
    for (int t = tid; t < 300; t += 128) {
        ((uint32_t*)(Qh + 49 * 40))[t] = 0;
        ((uint32_t*)(Vh + 49 * 40))[t] = 0;
    }

    // K,V fp16 loads: 32 halves = 4x16B per row
    {
        const uint4* kv = (const uint4*)(g_kv + (size_t)(b_ * NTOK) * 1024 + h * HD);
        for (int t = tid; t < NTOK * 4; t += 128) {
            int n = t >> 2, c = t & 3;
            ((uint4*)(Kh + n * 40))[c] = kv[(size_t)n * 128 + c];
            ((uint4*)(Vh + n * 40))[c] = kv[(size_t)n * 128 + 64 + c];
        }
    }
    // Q fp32 -> scaled fp16
    {
        const float4* qg = (const float4*)(q_global + (size_t)(b * NTOK) * CH + h * HD);
        for (int t = tid; t < NTOK * 8; t += 128) {
            int n = t >> 3, c = t & 7;
            float4 v = qg[(size_t)n * 128 + c];
            __half2* dst = (__half2*)(Qh + n * 40);
            dst[c * 2]     = __floats2half2_rn(v.x * SCALE, v.y * SCALE);
            dst[c * 2 + 1] = __floats2half2_rn(v.z * SCALE, v.w * SCALE);
        }
        for (int t = tid; t < 169; t += 128) bias_s[t] = bias_table[t * NH + h];
    }
    __syncthreads();

    const uint32_t qbu = s2u(Qh), kbu = s2u(Kh), vbu = s2u(Vh);
    const int lr = lane & 15;
    const int lc = (lane >> 4) * 8;   // half offset

    // ---- S = Q K^T ----
    float sacc[8][4];
    #pragma unroll
    for (int jt = 0; jt < 8; jt++)
        #pragma unroll
        for (int e = 0; e < 4; e++) sacc[jt][e] = 0.f;

    #pragma unroll
    for (int kt = 0; kt < 2; kt++) {
        uint32_t qa[4];
        LDSM4(qa, qbu + ((16 * wid + lr) * 40 + kt * 16 + lc) * 2);
        #pragma unroll
        for (int jt = 0; jt < 4; jt++) {
            uint32_t kf[4];
            LDSM4(kf, kbu + ((16 * jt + lr) * 40 + kt * 16 + lc) * 2);
            MMA16816(sacc[jt * 2 + 0], qa, kf[0], kf[2]);
            MMA16816(sacc[jt * 2 + 1], qa, kf[1], kf[3]);
        }
    }

    // ---- bias + mask ----
    const int r0 = 16 * wid + (lane >> 2);
    const int r1 = r0 + 8;
    const int ih0 = r0 / 7, iw0 = r0 - ih0 * 7;
    const int ih1 = r1 / 7, iw1 = r1 - ih1 * 7;
    #pragma unroll
    for (int jt = 0; jt < 8; jt++) {
        #pragma unroll
        for (int e = 0; e < 2; e++) {
            int j = jt * 8 + (lane & 3) * 2 + e;
            if (j < NTOK) {
                int jh = j / 7, jw = j - jh * 7;
                int i0 = (ih0 - jh + 6) * 13 + (iw0 - jw + 6);
                int i1 = (ih1 - jh + 6) * 13 + (iw1 - jw + 6);
                i0 = min(168, max(0, i0));
                i1 = min(168, max(0, i1));
                sacc[jt][e]     += bias_s[i0];
                sacc[jt][2 + e] += bias_s[i1];
            } else {
                sacc[jt][e]     = -1e30f;
                sacc[jt][2 + e] = -1e30f;
            }
        }
    }

    // ---- softmax (rows r0, r1; quad reduction) ----
    float m0 = -1e30f, m1 = -1e30f;
    #pragma unroll
    for (int jt = 0; jt < 8; jt++) {
        m0 = fmaxf(m0, fmaxf(sacc[jt][0], sacc[jt][1]));
        m1 = fmaxf(m1, fmaxf(sacc[jt][2], sacc[jt][3]));
    }
    m0 = fmaxf(m0, __shfl_xor_sync(0xffffffffu, m0, 1));
    m0 = fmaxf(m0, __shfl_xor_sync(0xffffffffu, m0, 2));
    m1 = fmaxf(m1, __shfl_xor_sync(0xffffffffu, m1, 1));
    m1 = fmaxf(m1, __shfl_xor_sync(0xffffffffu, m1, 2));
    float s0 = 0.f, s1 = 0.f;
    #pragma unroll
    for (int jt = 0; jt < 8; jt++) {
        sacc[jt][0] = __expf(sacc[jt][0] - m0); s0 += sacc[jt][0];
        sacc[jt][1] = __expf(sacc[jt][1] - m0); s0 += sacc[jt][1];
        sacc[jt][2] = __expf(sacc[jt][2] - m1); s1 += sacc[jt][2];
        sacc[jt][3] = __expf(sacc[jt][3] - m1); s1 += sacc[jt][3];
    }
    s0 += __shfl_xor_sync(0xffffffffu, s0, 1);
    s0 += __shfl_xor_sync(0xffffffffu, s0, 2);
    s1 += __shfl_xor_sync(0xffffffffu, s1, 1);
    s1 += __shfl_xor_sync(0xffffffffu, s1, 2);
    const float inv0 = 1.0f / s0, inv1 = 1.0f / s1;

    // pack P into fp16 A-fragments (C-frag layout == A-frag layout)
    uint32_t pa[4][4];
    #pragma unroll
    for (int kt = 0; kt < 4; kt++) {
        pa[kt][0] = packh2(sacc[2 * kt][0] * inv0,     sacc[2 * kt][1] * inv0);
        pa[kt][1] = packh2(sacc[2 * kt][2] * inv1,     sacc[2 * kt][3] * inv1);
        pa[kt][2] = packh2(sacc[2 * kt + 1][0] * inv0, sacc[2 * kt + 1][1] * inv0);
        pa[kt][3] = packh2(sacc[2 * kt + 1][2] * inv1, sacc[2 * kt + 1][3] * inv1);
    }

    // ---- X = P V ----
    float xacc[4][4];
    #pragma unroll
    for (int nt = 0; nt < 4; nt++)
        #pragma unroll
        for (int e = 0; e < 4; e++) xacc[nt][e] = 0.f;

    #pragma unroll
    for (int kt = 0; kt < 4; kt++) {
        uint32_t bv0[4], bv1[4];
        LDSM4T(bv0, vbu + ((16 * kt + lr) * 40 + lc) * 2);
        LDSM4T(bv1, vbu + ((16 * kt + lr) * 40 + 16 + lc) * 2);
        MMA16816(xacc[0], pa[kt], bv0[0], bv0[1]);
        MMA16816(xacc[1], pa[kt], bv0[2], bv0[3]);
        MMA16816(xacc[2], pa[kt], bv1[0], bv1[1]);
        MMA16816(xacc[3], pa[kt], bv1[2], bv1[3]);
    }

    // ---- write X as fp16 hi/lo ----
    if (r0 < NTOK) {
        size_t base = (size_t)(b_ * NTOK + r0) * CH + h * HD + (lane & 3) * 2;
        #pragma unroll
        for (int nt = 0; nt < 4; nt++) {
            float x0 = xacc[nt][0], x1 = xacc[nt][1];
            __half h0 = __float2half_rn(x0), h1 = __float2half_rn(x1);
            __half2 hv; hv.x = h0; hv.y = h1;
            *(__half2*)(g_xh + base + nt * 8) = hv;
            __half2 lv = __floats2half2_rn(x0 - __half2float(h0), x1 - __half2float(h1));
            *(__half2*)(g_xl + base + nt * 8) = lv;
        }
    }
    if (r1 < NTOK) {
        size_t base = (size_t)(b_ * NTOK + r1) * CH + h * HD + (lane & 3) * 2;
        #pragma unroll
        for (int nt = 0; nt < 4; nt++) {
            float x0 = xacc[nt][2], x1 = xacc[nt][3];
            __half h0 = __float2half_rn(x0), h1 = __float2half_rn(x1);
            __half2 hv; hv.x = h0; hv.y = h1;
            *(__half2*)(g_xh + base + nt * 8) = hv;
            __half2 lv = __floats2half2_rn(x0 - __half2float(h0), x1 - __half2float(h1));
            *(__half2*)(g_xl + base + nt * 8) = lv;
        }
    }
}

// ---------------------------------------------------------------------------
// Launch
// ---------------------------------------------------------------------------
extern "C" void kernel_launch(void* const* d_in, const int* in_sizes, int n_in,
                              void* d_out, int out_size)
{
    const float* inputs     = (const float*)d_in[0];
    const float* q_global   = (const float*)d_in[1];
    const float* qkv_w      = (const float*)d_in[2];
    const float* qkv_b      = (const float*)d_in[3];
    const float* bias_table = (const float*)d_in[4];
    const float* proj_w     = (const float*)d_in[5];
    const float* proj_b     = (const float*)d_in[6];
    float*       out        = (float*)d_out;

    __half *kv_ptr, *Ah, *Al, *Xh, *Xl, *W1h, *W2h;
    cudaGetSymbolAddress((void**)&kv_ptr, g_kv);
    cudaGetSymbolAddress((void**)&Ah,  g_Ah);
    cudaGetSymbolAddress((void**)&Al,  g_Al);
    cudaGetSymbolAddress((void**)&Xh,  g_xh);
    cudaGetSymbolAddress((void**)&Xl,  g_xl);
    cudaGetSymbolAddress((void**)&W1h, g_W1h);
    cudaGetSymbolAddress((void**)&W2h, g_W2h);

    cudaFuncSetAttribute(gemm_tc<true>,  cudaFuncAttributeMaxDynamicSharedMemorySize, SMEM_BYTES);
    cudaFuncSetAttribute(gemm_tc<false>, cudaFuncAttributeMaxDynamicSharedMemorySize, SMEM_BYTES);

    {
        int n4 = MTOT * KDIM / 4;
        split_kernel<<<(n4 + 255) / 256, 256>>>((const float4*)inputs, (uint2*)Ah, (uint2*)Al, n4);
        transpose_h<<<dim3(1024 / 32, 512 / 32), dim3(32, 8)>>>(qkv_w, W1h, 512, 1024);
        transpose_h<<<dim3(512 / 32, 512 / 32), dim3(32, 8)>>>(proj_w, W2h, 512, 512);
    }

    // 1) kv = inputs @ qkv_w + qkv_b  -> fp16
    gemm_tc<true><<<dim3(1024 / 128, MTOT / 128), 256, SMEM_BYTES>>>(
        Ah, Al, W1h, qkv_b, kv_ptr, 1024);

    // 2) attention (tensor-core)
    attn_tc<<<BWIN * NH, 128>>>(q_global, bias_table);

    // 3) out = x @ proj_w + proj_b -> fp32
    gemm_tc<false><<<dim3(512 / 128, MTOT / 128), 256, SMEM_BYTES>>>(
        Xh, Xl, W2h, proj_b, out, 512);
}

// round 11
// speedup vs baseline: 2.8928x; 1.5325x over previous
#include <cuda_runtime.h>
#include <cuda_fp16.h>
#include <cstdint>

// ---------------------------------------------------------------------------
// Problem constants
// ---------------------------------------------------------------------------
#define BWIN   1024
#define NTOK   49
#define CH     512
#define NH     16
#define HD     32
#define MTOT   (BWIN * NTOK)     // 50176
#define KDIM   512
#define BKE    32
#define KITERS (KDIM / BKE)      // 16
#define AST    40                // smem row stride (fp16 elems)
#define MAT_BYTES   (128 * AST * 2)      // 10240
#define STAGE_BYTES (2 * MAT_BYTES)      // 20480 (A,B)
#define SMEM_BYTES  (2 * STAGE_BYTES)    // 40960
#define SCALE  0.17677669529663687f

// ---------------------------------------------------------------------------
// Scratch
// ---------------------------------------------------------------------------
__device__ __half g_kv [(size_t)MTOT * 1024];   // kv projection, fp16
__device__ __half g_Ah [(size_t)MTOT * KDIM];   // inputs fp16
__device__ __half g_xh [(size_t)MTOT * KDIM];   // attention out fp16
__device__ __half g_W1h[1024 * 512];
__device__ __half g_W2h[ 512 * 512];

// ---------------------------------------------------------------------------
// Helpers
// ---------------------------------------------------------------------------
__device__ __forceinline__ uint32_t s2u(const void* p) {
    uint32_t a;
    asm("{ .reg .u64 t; cvta.to.shared.u64 t, %1; cvt.u32.u64 %0, t; }" : "=r"(a) : "l"(p));
    return a;
}

#define LDSM4(R, addr)                                                         \
    asm volatile("ldmatrix.sync.aligned.m8n8.x4.shared.b16 {%0,%1,%2,%3}, [%4];" \
                 : "=r"((R)[0]), "=r"((R)[1]), "=r"((R)[2]), "=r"((R)[3])       \
                 : "r"(addr))

#define LDSM4T(R, addr)                                                        \
    asm volatile("ldmatrix.sync.aligned.m8n8.x4.trans.shared.b16 {%0,%1,%2,%3}, [%4];" \
                 : "=r"((R)[0]), "=r"((R)[1]), "=r"((R)[2]), "=r"((R)[3])       \
                 : "r"(addr))

#define MMA16816(Cf, Af, b0, b1)                                               \
    asm volatile("mma.sync.aligned.m16n8k16.row.col.f32.f16.f16.f32 "          \
                 "{%0,%1,%2,%3}, {%4,%5,%6,%7}, {%8,%9}, {%0,%1,%2,%3};"       \
                 : "+f"((Cf)[0]), "+f"((Cf)[1]), "+f"((Cf)[2]), "+f"((Cf)[3])  \
                 : "r"((Af)[0]), "r"((Af)[1]), "r"((Af)[2]), "r"((Af)[3]),     \
                   "r"(b0), "r"(b1))

__device__ __forceinline__ uint32_t packh2(float a, float b) {
    __half2 h = __floats2half2_rn(a, b);
    return *reinterpret_cast<uint32_t*>(&h);
}

// ---------------------------------------------------------------------------
// Conversion kernels
// ---------------------------------------------------------------------------
__global__ void cvt_kernel(const float4* __restrict__ X, uint2* __restrict__ H, int n4) {
    int i = blockIdx.x * blockDim.x + threadIdx.x;
    if (i >= n4) return;
    float4 v = X[i];
    uint2 hv;
    hv.x = packh2(v.x, v.y); hv.y = packh2(v.z, v.w);
    H[i] = hv;
}

__global__ void transpose_h(const float* __restrict__ W,
                            __half* __restrict__ Th, int K, int N) {
    __shared__ float t[32][33];
    int n0 = blockIdx.x * 32, k0 = blockIdx.y * 32;
    for (int i = threadIdx.y; i < 32; i += 8)
        t[i][threadIdx.x] = W[(size_t)(k0 + i) * N + n0 + threadIdx.x];
    __syncthreads();
    for (int i = threadIdx.y; i < 32; i += 8)
        Th[(size_t)(n0 + i) * K + k0 + threadIdx.x] = __float2half_rn(t[threadIdx.x][i]);
}

// ---------------------------------------------------------------------------
// fp16 single-pass GEMM: C = A[M,K] @ B[N,K]^T + bias ; C fp32 or fp16
// 128x128 CTA tile, 8 warps of 64x32, double-buffered cp.async
// ---------------------------------------------------------------------------
__device__ __forceinline__ void fill_stage(uint32_t sbase,
                                           const __half* const srcs[2],
                                           int k0, int tid) {
    #pragma unroll
    for (int t = 0; t < 4; t++) {
        int c   = tid + t * 256;          // 0..1023
        int mat = c >> 9;                 // 0..1
        int r   = (c >> 2) & 127;
        int ch  = c & 3;
        uint32_t dst = sbase + mat * MAT_BYTES + r * (AST * 2) + ch * 16;
        const char* src = (const char*)(srcs[mat] + (size_t)r * KDIM + k0) + ch * 16;
        asm volatile("cp.async.cg.shared.global [%0], [%1], 16;" :: "r"(dst), "l"(src));
    }
    asm volatile("cp.async.commit_group;" ::: "memory");
}

template<bool OUTH>
__global__ void __launch_bounds__(256, 2) gemm_tc(
    const __half* __restrict__ A, const __half* __restrict__ B,
    const float* __restrict__ bias, void* __restrict__ Cv, int N)
{
    extern __shared__ char smem[];
    const uint32_t sb = s2u(smem);
    const int tid = threadIdx.x, wid = tid >> 5, lane = tid & 31;
    const int wm = (wid & 1) * 64;
    const int wn = (wid >> 1) * 32;
    const int bM = blockIdx.y * 128, bN = blockIdx.x * 128;

    const __half* srcs[2] = { A + (size_t)bM * KDIM, B + (size_t)bN * KDIM };

    float acc[4][4][4];
    #pragma unroll
    for (int i = 0; i < 4; i++)
        #pragma unroll
        for (int j = 0; j < 4; j++)
            #pragma unroll
            for (int e = 0; e < 4; e++) acc[i][j][e] = 0.f;

    const int lrow  = lane & 15;
    const int lcolB = ((lane >> 4) << 3) * 2;

    fill_stage(sb, srcs, 0, tid);

    for (int it = 0; it < KITERS; it++) {
        asm volatile("cp.async.wait_group 0;" ::: "memory");
        __syncthreads();

        uint32_t st = sb + (it & 1) * STAGE_BYTES;
        #pragma unroll
        for (int ks = 0; ks < 2; ks++) {
            uint32_t kb = ks * 32 + lcolB;
            uint32_t ah[4][4], bh[2][4];
            #pragma unroll
            for (int i = 0; i < 4; i++) {
                uint32_t ra = st + (wm + i * 16 + lrow) * (AST * 2) + kb;
                LDSM4(ah[i], ra);
            }
            #pragma unroll
            for (int jj = 0; jj < 2; jj++) {
                uint32_t rb = st + MAT_BYTES + (wn + jj * 16 + lrow) * (AST * 2) + kb;
                LDSM4(bh[jj], rb);
            }
            if (ks == 0 && it + 1 < KITERS)
                fill_stage(sb + ((it + 1) & 1) * STAGE_BYTES, srcs, (it + 1) * BKE, tid);

            #pragma unroll
            for (int i = 0; i < 4; i++)
                #pragma unroll
                for (int j = 0; j < 4; j++) {
                    int jj = j >> 1, sel = j & 1;
                    MMA16816(acc[i][j], ah[i], bh[jj][sel], bh[jj][sel + 2]);
                }
        }
    }

    #pragma unroll
    for (int j = 0; j < 4; j++) {
        int c0 = bN + wn + j * 8 + (lane & 3) * 2;
        float b0 = bias[c0], b1 = bias[c0 + 1];
        #pragma unroll
        for (int i = 0; i < 4; i++) {
            int r0 = bM + wm + i * 16 + (lane >> 2);
            if (OUTH) {
                __half* C = (__half*)Cv;
                __half2 v0 = __floats2half2_rn(acc[i][j][0] + b0, acc[i][j][1] + b1);
                __half2 v1 = __floats2half2_rn(acc[i][j][2] + b0, acc[i][j][3] + b1);
                *(__half2*)&C[(size_t)r0 * N + c0]       = v0;
                *(__half2*)&C[(size_t)(r0 + 8) * N + c0] = v1;
            } else {
                float* C = (float*)Cv;
                float2 v0 = { acc[i][j][0] + b0, acc[i][j][1] + b1 };
                float2 v1 = { acc[i][j][2] + b0, acc[i][j][3] + b1 };
                *(float2*)&C[(size_t)r0 * N + c0]       = v0;
                *(float2*)&C[(size_t)(r0 + 8) * N + c0] = v1;
            }
        }
    }
}

// ---------------------------------------------------------------------------
// Tensor-core attention: block = (window, head); 64x64 padded tiles
// ---------------------------------------------------------------------------
__global__ void __launch_bounds__(128) attn_tc(
    const float* __restrict__ q_global,
    const float* __restrict__ bias_table)
{
    const int bh = blockIdx.x;
    const int b_ = bh >> 4, h = bh & 15, b = b_ >> 4;
    const int tid = threadIdx.x, wid = tid >> 5, lane = tid & 31;

    __shared__ __align__(16) __half Qh[64 * 40];
    __shared__ __align__(16) __half Kh[64 * 40];
    __shared__ __align__(16) __half Vh[64 * 40];
    __shared__ float bias_s[172];

    // zero pad rows 49..63
    for (int t = tid; t < 300; t += 128) {
        ((uint32_t*)(Qh + 49 * 40))[t] = 0;
        ((uint32_t*)(Vh + 49 * 40))[t] = 0;
    }

    {
        const uint4* kv = (const uint4*)(g_kv + (size_t)(b_ * NTOK) * 1024 + h * HD);
        for (int t = tid; t < NTOK * 4; t += 128) {
            int n = t >> 2, c = t & 3;
            ((uint4*)(Kh + n * 40))[c] = kv[(size_t)n * 128 + c];
            ((uint4*)(Vh + n * 40))[c] = kv[(size_t)n * 128 + 64 + c];
        }
    }
    {
        const float4* qg = (const float4*)(q_global + (size_t)(b * NTOK) * CH + h * HD);
        for (int t = tid; t < NTOK * 8; t += 128) {
            int n = t >> 3, c = t & 7;
            float4 v = qg[(size_t)n * 128 + c];
            __half2* dst = (__half2*)(Qh + n * 40);
            dst[c * 2]     = __floats2half2_rn(v.x * SCALE, v.y * SCALE);
            dst[c * 2 + 1] = __floats2half2_rn(v.z * SCALE, v.w * SCALE);
        }
        for (int t = tid; t < 169; t += 128) bias_s[t] = bias_table[t * NH + h];
    }
    __syncthreads();

    const uint32_t qbu = s2u(Qh), kbu = s2u(Kh), vbu = s2u(Vh);
    const int lr = lane & 15;
    const int lc = (lane >> 4) * 8;

    // ---- S = Q K^T ----
    float sacc[8][4];
    #pragma unroll
    for (int jt = 0; jt < 8; jt++)
        #pragma unroll
        for (int e = 0; e < 4; e++) sacc[jt][e] = 0.f;

    #pragma unroll
    for (int kt = 0; kt < 2; kt++) {
        uint32_t qa[4];
        LDSM4(qa, qbu + ((16 * wid + lr) * 40 + kt * 16 + lc) * 2);
        #pragma unroll
        for (int jt = 0; jt < 4; jt++) {
            uint32_t kf[4];
            LDSM4(kf, kbu + ((16 * jt + lr) * 40 + kt * 16 + lc) * 2);
            MMA16816(sacc[jt * 2 + 0], qa, kf[0], kf[2]);
            MMA16816(sacc[jt * 2 + 1], qa, kf[1], kf[3]);
        }
    }

    // ---- bias + mask ----
    const int r0 = 16 * wid + (lane >> 2);
    const int r1 = r0 + 8;
    const int ih0 = r0 / 7, iw0 = r0 - ih0 * 7;
    const int ih1 = r1 / 7, iw1 = r1 - ih1 * 7;
    #pragma unroll
    for (int jt = 0; jt < 8; jt++) {
        #pragma unroll
        for (int e = 0; e < 2; e++) {
            int j = jt * 8 + (lane & 3) * 2 + e;
            if (j < NTOK) {
                int jh = j / 7, jw = j - jh * 7;
                int i0 = (ih0 - jh + 6) * 13 + (iw0 - jw + 6);
                int i1 = (ih1 - jh + 6) * 13 + (iw1 - jw + 6);
                i0 = min(168, max(0, i0));
                i1 = min(168, max(0, i1));
                sacc[jt][e]     += bias_s[i0];
                sacc[jt][2 + e] += bias_s[i1];
            } else {
                sacc[jt][e]     = -1e30f;
                sacc[jt][2 + e] = -1e30f;
            }
        }
    }

    // ---- softmax ----
    float m0 = -1e30f, m1 = -1e30f;
    #pragma unroll
    for (int jt = 0; jt < 8; jt++) {
        m0 = fmaxf(m0, fmaxf(sacc[jt][0], sacc[jt][1]));
        m1 = fmaxf(m1, fmaxf(sacc[jt][2], sacc[jt][3]));
    }
    m0 = fmaxf(m0, __shfl_xor_sync(0xffffffffu, m0, 1));
    m0 = fmaxf(m0, __shfl_xor_sync(0xffffffffu, m0, 2));
    m1 = fmaxf(m1, __shfl_xor_sync(0xffffffffu, m1, 1));
    m1 = fmaxf(m1, __shfl_xor_sync(0xffffffffu, m1, 2));
    float s0 = 0.f, s1 = 0.f;
    #pragma unroll
    for (int jt = 0; jt < 8; jt++) {
        sacc[jt][0] = __expf(sacc[jt][0] - m0); s0 += sacc[jt][0];
        sacc[jt][1] = __expf(sacc[jt][1] - m0); s0 += sacc[jt][1];
        sacc[jt][2] = __expf(sacc[jt][2] - m1); s1 += sacc[jt][2];
        sacc[jt][3] = __expf(sacc[jt][3] - m1); s1 += sacc[jt][3];
    }
    s0 += __shfl_xor_sync(0xffffffffu, s0, 1);
    s0 += __shfl_xor_sync(0xffffffffu, s0, 2);
    s1 += __shfl_xor_sync(0xffffffffu, s1, 1);
    s1 += __shfl_xor_sync(0xffffffffu, s1, 2);
    const float inv0 = 1.0f / s0, inv1 = 1.0f / s1;

    uint32_t pa[4][4];
    #pragma unroll
    for (int kt = 0; kt < 4; kt++) {
        pa[kt][0] = packh2(sacc[2 * kt][0] * inv0,     sacc[2 * kt][1] * inv0);
        pa[kt][1] = packh2(sacc[2 * kt][2] * inv1,     sacc[2 * kt][3] * inv1);
        pa[kt][2] = packh2(sacc[2 * kt + 1][0] * inv0, sacc[2 * kt + 1][1] * inv0);
        pa[kt][3] = packh2(sacc[2 * kt + 1][2] * inv1, sacc[2 * kt + 1][3] * inv1);
    }

    // ---- X = P V ----
    float xacc[4][4];
    #pragma unroll
    for (int nt = 0; nt < 4; nt++)
        #pragma unroll
        for (int e = 0; e < 4; e++) xacc[nt][e] = 0.f;

    #pragma unroll
    for (int kt = 0; kt < 4; kt++) {
        uint32_t bv0[4], bv1[4];
        LDSM4T(bv0, vbu + ((16 * kt + lr) * 40 + lc) * 2);
        LDSM4T(bv1, vbu + ((16 * kt + lr) * 40 + 16 + lc) * 2);
        MMA16816(xacc[0], pa[kt], bv0[0], bv0[1]);
        MMA16816(xacc[1], pa[kt], bv0[2], bv0[3]);
        MMA16816(xacc[2], pa[kt], bv1[0], bv1[1]);
        MMA16816(xacc[3], pa[kt], bv1[2], bv1[3]);
    }

    // ---- write X fp16 ----
    if (r0 < NTOK) {
        size_t base = (size_t)(b_ * NTOK + r0) * CH + h * HD + (lane & 3) * 2;
        #pragma unroll
        for (int nt = 0; nt < 4; nt++) {
            __half2 hv = __floats2half2_rn(xacc[nt][0], xacc[nt][1]);
            *(__half2*)(g_xh + base + nt * 8) = hv;
        }
    }
    if (r1 < NTOK) {
        size_t base = (size_t)(b_ * NTOK + r1) * CH + h * HD + (lane & 3) * 2;
        #pragma unroll
        for (int nt = 0; nt < 4; nt++) {
            __half2 hv = __floats2half2_rn(xacc[nt][2], xacc[nt][3]);
            *(__half2*)(g_xh + base + nt * 8) = hv;
        }
    }
}

// ---------------------------------------------------------------------------
// Launch
// ---------------------------------------------------------------------------
extern "C" void kernel_launch(void* const* d_in, const int* in_sizes, int n_in,
                              void* d_out, int out_size)
{
    const float* inputs     = (const float*)d_in[0];
    const float* q_global   = (const float*)d_in[1];
    const float* qkv_w      = (const float*)d_in[2];
    const float* qkv_b      = (const float*)d_in[3];
    const float* bias_table = (const float*)d_in[4];
    const float* proj_w     = (const float*)d_in[5];
    const float* proj_b     = (const float*)d_in[6];
    float*       out        = (float*)d_out;

    __half *kv_ptr, *Ah, *Xh, *W1h, *W2h;
    cudaGetSymbolAddress((void**)&kv_ptr, g_kv);
    cudaGetSymbolAddress((void**)&Ah,  g_Ah);
    cudaGetSymbolAddress((void**)&Xh,  g_xh);
    cudaGetSymbolAddress((void**)&W1h, g_W1h);
    cudaGetSymbolAddress((void**)&W2h, g_W2h);

    cudaFuncSetAttribute(gemm_tc<true>,  cudaFuncAttributeMaxDynamicSharedMemorySize, SMEM_BYTES);
    cudaFuncSetAttribute(gemm_tc<false>, cudaFuncAttributeMaxDynamicSharedMemorySize, SMEM_BYTES);

    {
        int n4 = MTOT * KDIM / 4;
        cvt_kernel<<<(n4 + 255) / 256, 256>>>((const float4*)inputs, (uint2*)Ah, n4);
        transpose_h<<<dim3(1024 / 32, 512 / 32), dim3(32, 8)>>>(qkv_w, W1h, 512, 1024);
        transpose_h<<<dim3(512 / 32, 512 / 32), dim3(32, 8)>>>(proj_w, W2h, 512, 512);
    }

    // 1) kv = inputs @ qkv_w + qkv_b  -> fp16
    gemm_tc<true><<<dim3(1024 / 128, MTOT / 128), 256, SMEM_BYTES>>>(
        Ah, W1h, qkv_b, kv_ptr, 1024);

    // 2) attention (tensor-core)
    attn_tc<<<BWIN * NH, 128>>>(q_global, bias_table);

    // 3) out = x @ proj_w + proj_b -> fp32
    gemm_tc<false><<<dim3(512 / 128, MTOT / 128), 256, SMEM_BYTES>>>(
        Xh, W2h, proj_b, out, 512);
}